// round 15
// baseline (speedup 1.0000x reference)
#include <cuda_runtime.h>
#include <cuda_fp16.h>
#include <math.h>
#include <stdint.h>

#define BB 64
#define NN 1024
#define DD 512
#define CC 512
#define KTOP 16
#define INV_TEMP (1.0f/0.07f)

// ---------------- scratch (device globals: no allocations allowed) ----------
__device__ __half g_aff[(size_t)BB * CC * NN];    // [b][c][n] normalized softmax p (fp16)
__device__ float g_rnt[CC];
__device__ float g_rnc[BB];
__device__ __half g_txh[(size_t)CC*DD];           // text fp16

// ================= helpers ====================================================
static __device__ __forceinline__ uint32_t smem_u32(const void* p){
    uint32_t a;
    asm("{ .reg .u64 t; cvta.to.shared.u64 t, %1; cvt.u32.u64 %0, t; }" : "=r"(a) : "l"(p));
    return a;
}
static __device__ __forceinline__ void cpasync16(uint32_t dst, const void* src){
    asm volatile("cp.async.cg.shared.global [%0], [%1], 16;" :: "r"(dst), "l"(src) : "memory");
}
static __device__ __forceinline__ uint32_t swz(uint32_t o){ return o ^ ((o >> 3) & 0x70u); }

static __device__ __forceinline__ void ldsm4(uint32_t &r0, uint32_t &r1,
                                             uint32_t &r2, uint32_t &r3, uint32_t addr){
    asm volatile("ldmatrix.sync.aligned.m8n8.x4.shared.b16 {%0,%1,%2,%3}, [%4];"
        : "=r"(r0), "=r"(r1), "=r"(r2), "=r"(r3) : "r"(addr));
}
static __device__ __forceinline__ void mma16816(float* d, const uint32_t* a,
                                                uint32_t b0, uint32_t b1){
    asm volatile("mma.sync.aligned.m16n8k16.row.col.f32.f16.f16.f32 "
        "{%0,%1,%2,%3}, {%4,%5,%6,%7}, {%8,%9}, {%0,%1,%2,%3};"
        : "+f"(d[0]), "+f"(d[1]), "+f"(d[2]), "+f"(d[3])
        : "r"(a[0]), "r"(a[1]), "r"(a[2]), "r"(a[3]), "r"(b0), "r"(b1));
}
static __device__ __forceinline__ unsigned umax2(unsigned a, unsigned b){ return a > b ? a : b; }

// ================= kernel 1: text fp16 convert + text/cls L2 norms ===========
__global__ void convert_kernel(const float* __restrict__ vcls,
                               const float* __restrict__ text){
    int w    = (blockIdx.x * blockDim.x + threadIdx.x) >> 5;
    int lane = threadIdx.x & 31;
    const int NW = CC + BB;
    if (w >= NW) return;
    const float* src; __half* hi = nullptr; float* rdst;
    if (w < CC){ src = text + (size_t)w*DD; hi = g_txh + (size_t)w*DD; rdst = g_rnt + w; }
    else       { int ci = w - CC; src = vcls + (size_t)ci*DD; rdst = g_rnc + ci; }
    float ss = 0.f;
    #pragma unroll
    for (int j = 0; j < 4; j++){
        int o = (j*32 + lane) * 4;
        float4 v = *reinterpret_cast<const float4*>(src + o);
        ss += v.x*v.x + v.y*v.y + v.z*v.z + v.w*v.w;
        if (hi){
            union { __half2 h2[2]; uint2 u; } P;
            P.h2[0] = __floats2half2_rn(v.x, v.y);
            P.h2[1] = __floats2half2_rn(v.z, v.w);
            *reinterpret_cast<uint2*>(hi + o) = P.u;
        }
    }
    #pragma unroll
    for (int off = 16; off; off >>= 1) ss += __shfl_xor_sync(0xffffffffu, ss, off);
    if (lane == 0) *rdst = 1.0f / fmaxf(sqrtf(ss), 1e-12f);
}

// ================= kernel 2: global affinity, writes 0.3*softmax ============
// text read as fp16 (g_txh) — runs after convert_kernel.
__global__ __launch_bounds__(512) void affg_kernel(const float* __restrict__ vcls,
                                                   float* __restrict__ out){
    __shared__ float sv[DD];
    __shared__ float red[16];
    int b = blockIdx.x, tid = threadIdx.x;
    sv[tid] = vcls[b*DD + tid];
    __syncthreads();
    const uint4* t4 = reinterpret_cast<const uint4*>(g_txh + (size_t)tid * DD);
    float dot = 0.f;
    #pragma unroll 8
    for (int k = 0; k < 64; k++){
        uint4 q = t4[k];
        float2 f0 = __half22float2(*reinterpret_cast<__half2*>(&q.x));
        float2 f1 = __half22float2(*reinterpret_cast<__half2*>(&q.y));
        float2 f2 = __half22float2(*reinterpret_cast<__half2*>(&q.z));
        float2 f3 = __half22float2(*reinterpret_cast<__half2*>(&q.w));
        const float* s = &sv[k*8];
        dot += f0.x*s[0] + f0.y*s[1] + f1.x*s[2] + f1.y*s[3]
             + f2.x*s[4] + f2.y*s[5] + f3.x*s[6] + f3.y*s[7];
    }
    float logit = dot * g_rnc[b] * g_rnt[tid] * INV_TEMP;
    int lane = tid & 31, wid = tid >> 5;
    float m = logit;
    #pragma unroll
    for (int off = 16; off; off >>= 1) m = fmaxf(m, __shfl_xor_sync(0xffffffffu, m, off));
    if (lane == 0) red[wid] = m;
    __syncthreads();
    float bm = red[0];
    #pragma unroll
    for (int i = 1; i < 16; i++) bm = fmaxf(bm, red[i]);
    __syncthreads();
    float e = __expf(logit - bm);
    float s = e;
    #pragma unroll
    for (int off = 16; off; off >>= 1) s += __shfl_xor_sync(0xffffffffu, s, off);
    if (lane == 0) red[wid] = s;
    __syncthreads();
    float bs = 0.f;
    #pragma unroll
    for (int i = 0; i < 16; i++) bs += red[i];
    out[b*CC + tid] = 0.3f * e / bs;
}

// ================= kernel 3: fp16 HMMA GEMM, 16 warps, fused A ==============
// CTA: 64 patches x 512 classes, 512 threads (16 warps: mw=wid>>3, nw=wid&7).
// Warp tile 32x64. kc=64, 8 k-iters. B triple-buffered, A double-buffered,
// head-barrier-only pipeline (loads issued AFTER the MMA region, no tail sync).
#define SM_A0   0u
#define SM_A1   8192u
#define SM_B0   16384u
#define SM_B1   81920u
#define SM_B2   147456u
#define SM_AUX  212992u
#define SM_DYN  (212992u + 4864u + 1024u)

static __device__ __forceinline__ void issueB(int kt, uint32_t b_dst, int tid){
    const __half* Bb = g_txh + kt * 64;
    #pragma unroll
    for (int t = 0; t < 8; t++){   // B: 512 rows x 128B = 4096 chunks / 512 thr
        int g = tid + t*512; int row = g >> 3; int c = g & 7;
        cpasync16(b_dst + swz(row*128 + c*16), Bb + (size_t)row*DD + c*8);
    }
    asm volatile("cp.async.commit_group;" ::: "memory");
}

// convert & store 2 rows' chunks of A (rows rw, rw+32; 16B chunk c16), sumsq
static __device__ __forceinline__ void stsA(uint32_t abase, int rw, int c16,
                                            const float4* pf, float* ss){
    #pragma unroll
    for (int i = 0; i < 2; i++){
        union { __half2 h2; uint32_t u; } P0, P1;
        P0.h2 = __floats2half2_rn(pf[i].x, pf[i].y);
        P1.h2 = __floats2half2_rn(pf[i].z, pf[i].w);
        ss[i] += pf[i].x*pf[i].x + pf[i].y*pf[i].y + pf[i].z*pf[i].z + pf[i].w*pf[i].w;
        uint32_t off = (uint32_t)((rw + 32*i)*128 + c16*8);
        asm volatile("st.shared.v2.b32 [%0], {%1,%2};"
            :: "r"(abase + swz(off)), "r"(P0.u), "r"(P1.u) : "memory");
    }
}

__global__ __launch_bounds__(512, 1) void gemm_softmax_kernel(const float* __restrict__ vp){
    extern __shared__ __align__(16) char dsm[];
    const uint32_t raw  = smem_u32(dsm);
    const uint32_t base = (raw + 1023u) & ~1023u;
    char* bp = dsm + (base - raw);

    const int tid = threadIdx.x;
    const int pb  = blockIdx.x;          // 0..1023
    const int b   = pb >> 4;
    const int nt  = pb & 15;

    const uint32_t ab[2]   = { base + SM_A0, base + SM_A1 };
    const uint32_t bbuf[3] = { base + SM_B0, base + SM_B1, base + SM_B2 };
    float* s_t    = reinterpret_cast<float*>(bp);                    // 512*68 f (overlays stages)
    float* s_rnt  = reinterpret_cast<float*>(bp + SM_AUX);           // 512 f
    float* s_rnp  = reinterpret_cast<float*>(bp + SM_AUX + 2048);    // 64 f
    float* s_red  = reinterpret_cast<float*>(bp + SM_AUX + 2304);    // 64*8 f
    float* s_gmax = reinterpret_cast<float*>(bp + SM_AUX + 4352);    // 64 f
    float* s_rzv  = reinterpret_cast<float*>(bp + SM_AUX + 4608);    // 64 f

    const int wid  = tid >> 5;
    const int lane = tid & 31;
    const int mw   = wid >> 3;           // 0..1
    const int nw   = wid & 7;            // 0..7
    const int gid  = lane >> 2;          // row group 0..7
    const int tig  = lane & 3;

    if (tid < 512) s_rnt[tid] = g_rnt[tid];

    // fused A path: 1024 float4 chunks per k-tile, 2 per thread (rows rw, rw+32)
    const int c16 = tid & 15;            // 16B chunk within 64-float slab row
    const int rw  = tid >> 4;            // row 0..31; second row = rw+32
    const float* Ag = vp + ((size_t)(pb*64 + rw))*DD + c16*4;

    float4 pf[2];
    pf[0] = *reinterpret_cast<const float4*>(Ag);
    pf[1] = *reinterpret_cast<const float4*>(Ag + (size_t)32*DD);

    issueB(0, bbuf[0], tid);
    issueB(1, bbuf[1], tid);

    float ss[2] = {0.f, 0.f};
    stsA(ab[0], rw, c16, pf, ss);                        // A tile for kt=0
    pf[0] = *reinterpret_cast<const float4*>(Ag + 64);
    pf[1] = *reinterpret_cast<const float4*>(Ag + (size_t)32*DD + 64);

    // ldmatrix lane addressing (canonical x4 fragment order)
    const int lr = (lane & 7) + ((lane >> 3) & 1) * 8;   // row within 16
    const int lk = (lane >> 4) * 16;                     // 16B col half

    float acc[2][8][4];
    #pragma unroll
    for (int mi = 0; mi < 2; mi++)
        #pragma unroll
        for (int j = 0; j < 8; j++)
            #pragma unroll
            for (int v = 0; v < 4; v++) acc[mi][j][v] = 0.f;

    int b3 = 0;                          // it % 3
    for (int it = 0; it < 8; ++it){
        if (it == 7) asm volatile("cp.async.wait_group 0;" ::: "memory");
        else         asm volatile("cp.async.wait_group 1;" ::: "memory");
        __syncthreads();                 // head barrier (the only one per iter)

        const uint32_t abase = ab[it & 1];
        const uint32_t bbase = bbuf[b3];
        #pragma unroll
        for (int ks = 0; ks < 4; ks++){
            uint32_t af[2][4];
            #pragma unroll
            for (int mi = 0; mi < 2; mi++){
                int r = mw*32 + mi*16 + lr;
                ldsm4(af[mi][0], af[mi][1], af[mi][2], af[mi][3],
                      abase + swz((uint32_t)(r*128 + ks*32 + lk)));
            }
            uint32_t bf[4][4];
            #pragma unroll
            for (int jj = 0; jj < 4; jj++){
                int r = nw*64 + jj*16 + lr;
                ldsm4(bf[jj][0], bf[jj][1], bf[jj][2], bf[jj][3],
                      bbase + swz((uint32_t)(r*128 + ks*32 + lk)));
            }
            #pragma unroll
            for (int mi = 0; mi < 2; mi++)
                #pragma unroll
                for (int j = 0; j < 8; j++)
                    mma16816(acc[mi][j], af[mi], bf[j>>1][j&1], bf[j>>1][(j&1)+2]);
        }
        // post-MMA, no tail barrier: write A for it+1 (buffer consumed at it-1),
        // issue B for it+2 into stage consumed at it-1 — both safe past head sync.
        if (it + 1 < 8) stsA(ab[(it+1)&1], rw, c16, pf, ss);
        if (it + 2 < 8){
            pf[0] = *reinterpret_cast<const float4*>(Ag + (it+2)*64);
            pf[1] = *reinterpret_cast<const float4*>(Ag + (size_t)32*DD + (it+2)*64);
            int nb = b3 + 2; if (nb >= 3) nb -= 3;
            issueB(it + 2, bbuf[nb], tid);
        }
        b3++; if (b3 >= 3) b3 -= 3;
    }
    __syncthreads();                     // stages dead; s_t overlay begins

    // patch norms: reduce sumsq over the 16-lane group sharing each row
    #pragma unroll
    for (int i = 0; i < 2; i++){
        float s = ss[i];
        s += __shfl_xor_sync(0xffffffffu, s, 1);
        s += __shfl_xor_sync(0xffffffffu, s, 2);
        s += __shfl_xor_sync(0xffffffffu, s, 4);
        s += __shfl_xor_sync(0xffffffffu, s, 8);
        if (c16 == 0) s_rnp[rw + 32*i] = 1.0f / fmaxf(sqrtf(s), 1e-12f);
    }
    __syncthreads();

    // ---- epilogue: scale, softmax over full 512 cols, normalized fp16 store
    float rs[2][2], rt[8][2];
    #pragma unroll
    for (int mi = 0; mi < 2; mi++)
        #pragma unroll
        for (int h = 0; h < 2; h++)
            rs[mi][h] = s_rnp[mw*32 + mi*16 + h*8 + gid] * INV_TEMP;
    #pragma unroll
    for (int j = 0; j < 8; j++){
        int c0 = nw*64 + j*8 + tig*2;
        rt[j][0] = s_rnt[c0]; rt[j][1] = s_rnt[c0+1];
    }
    #pragma unroll
    for (int mi = 0; mi < 2; mi++)
        #pragma unroll
        for (int j = 0; j < 8; j++)
            #pragma unroll
            for (int v = 0; v < 4; v++)
                acc[mi][j][v] *= rs[mi][v>>1] * rt[j][v&1];

    // per-row max (warp slice over its 64 cols), quad shuffle, 8-warp smem reduce
    #pragma unroll
    for (int mi = 0; mi < 2; mi++)
        #pragma unroll
        for (int h = 0; h < 2; h++){
            float mx = -3.0e38f;
            #pragma unroll
            for (int j = 0; j < 8; j++)
                mx = fmaxf(mx, fmaxf(acc[mi][j][2*h], acc[mi][j][2*h+1]));
            mx = fmaxf(mx, __shfl_xor_sync(0xffffffffu, mx, 1));
            mx = fmaxf(mx, __shfl_xor_sync(0xffffffffu, mx, 2));
            if (tig == 0) s_red[(mw*32 + mi*16 + h*8 + gid)*8 + nw] = mx;
        }
    __syncthreads();
    if (tid < 64){
        float m = s_red[tid*8];
        #pragma unroll
        for (int k = 1; k < 8; k++) m = fmaxf(m, s_red[tid*8 + k]);
        s_gmax[tid] = m;
    }
    __syncthreads();

    // exp + row sum
    #pragma unroll
    for (int mi = 0; mi < 2; mi++)
        #pragma unroll
        for (int h = 0; h < 2; h++){
            float gm = s_gmax[mw*32 + mi*16 + h*8 + gid];
            float sm = 0.f;
            #pragma unroll
            for (int j = 0; j < 8; j++){
                float e0 = __expf(acc[mi][j][2*h]   - gm);
                float e1 = __expf(acc[mi][j][2*h+1] - gm);
                acc[mi][j][2*h] = e0; acc[mi][j][2*h+1] = e1;
                sm += e0 + e1;
            }
            sm += __shfl_xor_sync(0xffffffffu, sm, 1);
            sm += __shfl_xor_sync(0xffffffffu, sm, 2);
            if (tig == 0) s_red[(mw*32 + mi*16 + h*8 + gid)*8 + nw] = sm;
        }
    __syncthreads();
    if (tid < 64){
        float s = 0.f;
        #pragma unroll
        for (int k = 0; k < 8; k++) s += s_red[tid*8 + k];
        s_rzv[tid] = 1.0f / s;
    }
    __syncthreads();

    // normalized transposed store into padded smem [c][n], stride 68
    #pragma unroll
    for (int mi = 0; mi < 2; mi++)
        #pragma unroll
        for (int j = 0; j < 8; j++)
            #pragma unroll
            for (int v = 0; v < 4; v++){
                int col = nw*64 + j*8 + tig*2 + (v&1);
                int row = mw*32 + mi*16 + (v>>1)*8 + gid;
                s_t[col*68 + row] = acc[mi][j][v] * s_rzv[row];
            }
    __syncthreads();

    // vectorized coalesced fp16 copy-out: g_aff[b][c][nt*64 + n]
    __half* obase = g_aff + (size_t)b * CC * NN + (size_t)nt * 64;
    const int cpart = tid >> 4;           // 0..31
    const int n4    = (tid & 15) * 4;     // 0..60
    #pragma unroll 4
    for (int itc = 0; itc < 16; itc++){
        int c = itc*32 + cpart;
        float4 f = *reinterpret_cast<const float4*>(&s_t[c*68 + n4]);
        union { __half2 h[2]; uint2 u; } U;
        U.h[0] = __floats2half2_rn(f.x, f.y);
        U.h[1] = __floats2half2_rn(f.z, f.w);
        *reinterpret_cast<uint2*>(obase + (size_t)c * NN + n4) = U.u;
    }
}

// ================= kernel 4: top-16 over N per (b,c), blend ==================
// Per-lane value + chunk-key arrays live in SMEM (warp-private, no barriers).
// key = (fp16bits << 16) | (lane << 3) | chunk
__global__ __launch_bounds__(256) void topk_kernel(float* __restrict__ out){
    __shared__ uint32_t s_v[8][16][32];   // [warp][reg][lane]  values (reg-major)
    __shared__ uint32_t s_k[8][32][8];    // [warp][lane][chunk] keys (lane-major)

    const int wip  = threadIdx.x >> 5;                  // warp in block
    const int lane = threadIdx.x & 31;
    const int w    = blockIdx.x * 8 + wip;              // b*512 + c
    if (w >= BB*CC) return;
    const uint4* p = reinterpret_cast<const uint4*>(g_aff + (size_t)w * NN);

    uint32_t (*V)[32] = s_v[wip];
    uint32_t* K = s_k[wip][lane];

    unsigned lk = 0;
    #pragma unroll
    for (int j = 0; j < 4; j++){
        uint4 q = p[j*32 + lane];
        V[4*j+0][lane] = q.x; V[4*j+1][lane] = q.y;
        V[4*j+2][lane] = q.z; V[4*j+3][lane] = q.w;
        unsigned m0 = __vmaxu2(q.x, q.y);
        unsigned mv0 = umax2(m0 & 0xFFFFu, m0 >> 16);
        unsigned k0 = (mv0 << 16) | ((unsigned)lane << 3) | (unsigned)(2*j);
        unsigned m1 = __vmaxu2(q.z, q.w);
        unsigned mv1 = umax2(m1 & 0xFFFFu, m1 >> 16);
        unsigned k1 = (mv1 << 16) | ((unsigned)lane << 3) | (unsigned)(2*j + 1);
        K[2*j] = k0; K[2*j+1] = k1;
        lk = umax2(lk, umax2(k0, k1));
    }

    float sum = 0.f;
    #pragma unroll
    for (int it = 0; it < KTOP; ++it){
        unsigned m;
        asm("redux.sync.max.u32 %0, %1, 0xffffffff;" : "=r"(m) : "r"(lk));
        __half_raw hr; hr.x = (unsigned short)(m >> 16);
        sum += __half2float(*reinterpret_cast<__half*>(&hr));
        if (((m >> 3) & 31u) == (unsigned)lane){
            const unsigned val = m >> 16;
            const int oc = (int)(m & 7u);
            unsigned v0 = V[2*oc  ][lane];
            unsigned v1 = V[2*oc+1][lane];
            if      ((v0 & 0xFFFFu) == val) v0 &= 0xFFFF0000u;
            else if ((v0 >> 16)     == val) v0 &= 0x0000FFFFu;
            else if ((v1 & 0xFFFFu) == val) v1 &= 0xFFFF0000u;
            else                            v1 &= 0x0000FFFFu;
            V[2*oc  ][lane] = v0;
            V[2*oc+1][lane] = v1;
            unsigned m2 = __vmaxu2(v0, v1);
            unsigned mv = umax2(m2 & 0xFFFFu, m2 >> 16);
            K[oc] = (mv << 16) | ((unsigned)lane << 3) | (unsigned)oc;
            uint4 ka = *reinterpret_cast<uint4*>(&K[0]);
            uint4 kb = *reinterpret_cast<uint4*>(&K[4]);
            unsigned t0 = umax2(ka.x, ka.y), t1 = umax2(ka.z, ka.w);
            unsigned t2 = umax2(kb.x, kb.y), t3 = umax2(kb.z, kb.w);
            lk = umax2(umax2(t0, t1), umax2(t2, t3));
        }
    }
    if (lane == 0) out[w] += 0.7f * (sum * (1.0f / (float)KTOP));
}

// ================= launch =====================================================
// DAG: convert -> {affg, gemm} (parallel, fork-join via events) -> topk.
extern "C" void kernel_launch(void* const* d_in, const int* in_sizes, int n_in,
                              void* d_out, int out_size){
    const float* vcls = nullptr;
    const float* vp   = nullptr;
    const float* text = nullptr;
    for (int i = 0; i < n_in; i++){
        if      (in_sizes[i] == BB*DD)     vcls = (const float*)d_in[i];
        else if (in_sizes[i] == BB*NN*DD)  vp   = (const float*)d_in[i];
        else if (in_sizes[i] == CC*DD)     text = (const float*)d_in[i];
    }
    float* out = (float*)d_out;

    // one-time setup (host-side objects only; no device allocations)
    static cudaStream_t s_side = nullptr;
    static cudaEvent_t  e_fork = nullptr, e_join = nullptr;
    if (!s_side){
        cudaStreamCreateWithFlags(&s_side, cudaStreamNonBlocking);
        cudaEventCreateWithFlags(&e_fork, cudaEventDisableTiming);
        cudaEventCreateWithFlags(&e_join, cudaEventDisableTiming);
        cudaFuncSetAttribute(gemm_softmax_kernel,
                             cudaFuncAttributeMaxDynamicSharedMemorySize, SM_DYN);
    }

    const int nwarps = CC + BB;
    convert_kernel<<<(nwarps*32 + 255)/256, 256>>>(vcls, text);
    cudaEventRecord(e_fork, 0);                         // fork after convert
    cudaStreamWaitEvent(s_side, e_fork, 0);
    gemm_softmax_kernel<<<1024, 512, SM_DYN, s_side>>>(vp);   // big kernel on side
    affg_kernel<<<BB, 512>>>(vcls, out);                      // small kernel hides under it
    cudaEventRecord(e_join, s_side);
    cudaStreamWaitEvent(0, e_join, 0);                  // join before topk
    topk_kernel<<<(BB*CC)/8, 256>>>(out);
}

// round 16
// speedup vs baseline: 1.1740x; 1.1740x over previous
#include <cuda_runtime.h>
#include <cuda_fp16.h>
#include <math.h>
#include <stdint.h>

#define BB 64
#define NN 1024
#define DD 512
#define CC 512
#define KTOP 16
#define INV_TEMP (1.0f/0.07f)

// ---------------- scratch (device globals: no allocations allowed) ----------
__device__ __half g_aff[(size_t)BB * CC * NN];    // [b][c][n] normalized softmax p (fp16)
__device__ float g_rnt[CC];
__device__ float g_rnc[BB];
__device__ __half g_txh[(size_t)CC*DD];           // text fp16

// ================= helpers ====================================================
static __device__ __forceinline__ uint32_t smem_u32(const void* p){
    uint32_t a;
    asm("{ .reg .u64 t; cvta.to.shared.u64 t, %1; cvt.u32.u64 %0, t; }" : "=r"(a) : "l"(p));
    return a;
}
static __device__ __forceinline__ void cpasync16(uint32_t dst, const void* src){
    asm volatile("cp.async.cg.shared.global [%0], [%1], 16;" :: "r"(dst), "l"(src) : "memory");
}
static __device__ __forceinline__ uint32_t swz(uint32_t o){ return o ^ ((o >> 3) & 0x70u); }

static __device__ __forceinline__ void ldsm4(uint32_t &r0, uint32_t &r1,
                                             uint32_t &r2, uint32_t &r3, uint32_t addr){
    asm volatile("ldmatrix.sync.aligned.m8n8.x4.shared.b16 {%0,%1,%2,%3}, [%4];"
        : "=r"(r0), "=r"(r1), "=r"(r2), "=r"(r3) : "r"(addr));
}
static __device__ __forceinline__ void mma16816(float* d, const uint32_t* a,
                                                uint32_t b0, uint32_t b1){
    asm volatile("mma.sync.aligned.m16n8k16.row.col.f32.f16.f16.f32 "
        "{%0,%1,%2,%3}, {%4,%5,%6,%7}, {%8,%9}, {%0,%1,%2,%3};"
        : "+f"(d[0]), "+f"(d[1]), "+f"(d[2]), "+f"(d[3])
        : "r"(a[0]), "r"(a[1]), "r"(a[2]), "r"(a[3]), "r"(b0), "r"(b1));
}
static __device__ __forceinline__ unsigned umax2(unsigned a, unsigned b){ return a > b ? a : b; }

// ================= kernel 1: text fp16 convert + text/cls L2 norms ===========
__global__ void convert_kernel(const float* __restrict__ vcls,
                               const float* __restrict__ text){
    int w    = (blockIdx.x * blockDim.x + threadIdx.x) >> 5;
    int lane = threadIdx.x & 31;
    const int NW = CC + BB;
    if (w >= NW) return;
    const float* src; __half* hi = nullptr; float* rdst;
    if (w < CC){ src = text + (size_t)w*DD; hi = g_txh + (size_t)w*DD; rdst = g_rnt + w; }
    else       { int ci = w - CC; src = vcls + (size_t)ci*DD; rdst = g_rnc + ci; }
    float ss = 0.f;
    #pragma unroll
    for (int j = 0; j < 4; j++){
        int o = (j*32 + lane) * 4;
        float4 v = *reinterpret_cast<const float4*>(src + o);
        ss += v.x*v.x + v.y*v.y + v.z*v.z + v.w*v.w;
        if (hi){
            union { __half2 h2[2]; uint2 u; } P;
            P.h2[0] = __floats2half2_rn(v.x, v.y);
            P.h2[1] = __floats2half2_rn(v.z, v.w);
            *reinterpret_cast<uint2*>(hi + o) = P.u;
        }
    }
    #pragma unroll
    for (int off = 16; off; off >>= 1) ss += __shfl_xor_sync(0xffffffffu, ss, off);
    if (lane == 0) *rdst = 1.0f / fmaxf(sqrtf(ss), 1e-12f);
}

// ================= kernel 2: global affinity, writes 0.3*softmax ============
// text read as fp16 (g_txh) — runs after convert_kernel.
__global__ __launch_bounds__(512) void affg_kernel(const float* __restrict__ vcls,
                                                   float* __restrict__ out){
    __shared__ float sv[DD];
    __shared__ float red[16];
    int b = blockIdx.x, tid = threadIdx.x;
    sv[tid] = vcls[b*DD + tid];
    __syncthreads();
    const uint4* t4 = reinterpret_cast<const uint4*>(g_txh + (size_t)tid * DD);
    float dot = 0.f;
    #pragma unroll 8
    for (int k = 0; k < 64; k++){
        uint4 q = t4[k];
        float2 f0 = __half22float2(*reinterpret_cast<__half2*>(&q.x));
        float2 f1 = __half22float2(*reinterpret_cast<__half2*>(&q.y));
        float2 f2 = __half22float2(*reinterpret_cast<__half2*>(&q.z));
        float2 f3 = __half22float2(*reinterpret_cast<__half2*>(&q.w));
        const float* s = &sv[k*8];
        dot += f0.x*s[0] + f0.y*s[1] + f1.x*s[2] + f1.y*s[3]
             + f2.x*s[4] + f2.y*s[5] + f3.x*s[6] + f3.y*s[7];
    }
    float logit = dot * g_rnc[b] * g_rnt[tid] * INV_TEMP;
    int lane = tid & 31, wid = tid >> 5;
    float m = logit;
    #pragma unroll
    for (int off = 16; off; off >>= 1) m = fmaxf(m, __shfl_xor_sync(0xffffffffu, m, off));
    if (lane == 0) red[wid] = m;
    __syncthreads();
    float bm = red[0];
    #pragma unroll
    for (int i = 1; i < 16; i++) bm = fmaxf(bm, red[i]);
    __syncthreads();
    float e = __expf(logit - bm);
    float s = e;
    #pragma unroll
    for (int off = 16; off; off >>= 1) s += __shfl_xor_sync(0xffffffffu, s, off);
    if (lane == 0) red[wid] = s;
    __syncthreads();
    float bs = 0.f;
    #pragma unroll
    for (int i = 0; i < 16; i++) bs += red[i];
    out[b*CC + tid] = 0.3f * e / bs;
}

// ================= kernel 3: fp16 HMMA GEMM, 16 warps, fused A ==============
// CTA: 64 patches x 512 classes, 512 threads (16 warps: mw=wid>>3, nw=wid&7).
// Warp tile 32x64. kc=64, 8 k-iters. B triple-buffered, A double-buffered,
// head-barrier-only pipeline (loads issued AFTER the MMA region, no tail sync).
#define SM_A0   0u
#define SM_A1   8192u
#define SM_B0   16384u
#define SM_B1   81920u
#define SM_B2   147456u
#define SM_AUX  212992u
#define SM_DYN  (212992u + 4864u + 1024u)

static __device__ __forceinline__ void issueB(int kt, uint32_t b_dst, int tid){
    const __half* Bb = g_txh + kt * 64;
    #pragma unroll
    for (int t = 0; t < 8; t++){   // B: 512 rows x 128B = 4096 chunks / 512 thr
        int g = tid + t*512; int row = g >> 3; int c = g & 7;
        cpasync16(b_dst + swz(row*128 + c*16), Bb + (size_t)row*DD + c*8);
    }
    asm volatile("cp.async.commit_group;" ::: "memory");
}

// convert & store 2 rows' chunks of A (rows rw, rw+32; 16B chunk c16), sumsq
static __device__ __forceinline__ void stsA(uint32_t abase, int rw, int c16,
                                            const float4* pf, float* ss){
    #pragma unroll
    for (int i = 0; i < 2; i++){
        union { __half2 h2; uint32_t u; } P0, P1;
        P0.h2 = __floats2half2_rn(pf[i].x, pf[i].y);
        P1.h2 = __floats2half2_rn(pf[i].z, pf[i].w);
        ss[i] += pf[i].x*pf[i].x + pf[i].y*pf[i].y + pf[i].z*pf[i].z + pf[i].w*pf[i].w;
        uint32_t off = (uint32_t)((rw + 32*i)*128 + c16*8);
        asm volatile("st.shared.v2.b32 [%0], {%1,%2};"
            :: "r"(abase + swz(off)), "r"(P0.u), "r"(P1.u) : "memory");
    }
}

__global__ __launch_bounds__(512, 1) void gemm_softmax_kernel(const float* __restrict__ vp){
    extern __shared__ __align__(16) char dsm[];
    const uint32_t raw  = smem_u32(dsm);
    const uint32_t base = (raw + 1023u) & ~1023u;
    char* bp = dsm + (base - raw);

    const int tid = threadIdx.x;
    const int pb  = blockIdx.x;          // 0..1023
    const int b   = pb >> 4;
    const int nt  = pb & 15;

    const uint32_t ab[2]   = { base + SM_A0, base + SM_A1 };
    const uint32_t bbuf[3] = { base + SM_B0, base + SM_B1, base + SM_B2 };
    float* s_t    = reinterpret_cast<float*>(bp);                    // 512*68 f (overlays stages)
    float* s_rnt  = reinterpret_cast<float*>(bp + SM_AUX);           // 512 f
    float* s_rnp  = reinterpret_cast<float*>(bp + SM_AUX + 2048);    // 64 f
    float* s_red  = reinterpret_cast<float*>(bp + SM_AUX + 2304);    // 64*8 f
    float* s_gmax = reinterpret_cast<float*>(bp + SM_AUX + 4352);    // 64 f
    float* s_rzv  = reinterpret_cast<float*>(bp + SM_AUX + 4608);    // 64 f

    const int wid  = tid >> 5;
    const int lane = tid & 31;
    const int mw   = wid >> 3;           // 0..1
    const int nw   = wid & 7;            // 0..7
    const int gid  = lane >> 2;          // row group 0..7
    const int tig  = lane & 3;

    if (tid < 512) s_rnt[tid] = g_rnt[tid];

    // fused A path: 1024 float4 chunks per k-tile, 2 per thread (rows rw, rw+32)
    const int c16 = tid & 15;            // 16B chunk within 64-float slab row
    const int rw  = tid >> 4;            // row 0..31; second row = rw+32
    const float* Ag = vp + ((size_t)(pb*64 + rw))*DD + c16*4;

    float4 pf[2];
    pf[0] = *reinterpret_cast<const float4*>(Ag);
    pf[1] = *reinterpret_cast<const float4*>(Ag + (size_t)32*DD);

    issueB(0, bbuf[0], tid);
    issueB(1, bbuf[1], tid);

    float ss[2] = {0.f, 0.f};
    stsA(ab[0], rw, c16, pf, ss);                        // A tile for kt=0
    pf[0] = *reinterpret_cast<const float4*>(Ag + 64);
    pf[1] = *reinterpret_cast<const float4*>(Ag + (size_t)32*DD + 64);

    // ldmatrix lane addressing (canonical x4 fragment order)
    const int lr = (lane & 7) + ((lane >> 3) & 1) * 8;   // row within 16
    const int lk = (lane >> 4) * 16;                     // 16B col half

    float acc[2][8][4];
    #pragma unroll
    for (int mi = 0; mi < 2; mi++)
        #pragma unroll
        for (int j = 0; j < 8; j++)
            #pragma unroll
            for (int v = 0; v < 4; v++) acc[mi][j][v] = 0.f;

    int b3 = 0;                          // it % 3
    for (int it = 0; it < 8; ++it){
        if (it == 7) asm volatile("cp.async.wait_group 0;" ::: "memory");
        else         asm volatile("cp.async.wait_group 1;" ::: "memory");
        __syncthreads();                 // head barrier (the only one per iter)

        const uint32_t abase = ab[it & 1];
        const uint32_t bbase = bbuf[b3];
        #pragma unroll
        for (int ks = 0; ks < 4; ks++){
            uint32_t af[2][4];
            #pragma unroll
            for (int mi = 0; mi < 2; mi++){
                int r = mw*32 + mi*16 + lr;
                ldsm4(af[mi][0], af[mi][1], af[mi][2], af[mi][3],
                      abase + swz((uint32_t)(r*128 + ks*32 + lk)));
            }
            uint32_t bf[4][4];
            #pragma unroll
            for (int jj = 0; jj < 4; jj++){
                int r = nw*64 + jj*16 + lr;
                ldsm4(bf[jj][0], bf[jj][1], bf[jj][2], bf[jj][3],
                      bbase + swz((uint32_t)(r*128 + ks*32 + lk)));
            }
            #pragma unroll
            for (int mi = 0; mi < 2; mi++)
                #pragma unroll
                for (int j = 0; j < 8; j++)
                    mma16816(acc[mi][j], af[mi], bf[j>>1][j&1], bf[j>>1][(j&1)+2]);
        }
        // post-MMA, no tail barrier: write A for it+1 (buffer consumed at it-1),
        // issue B for it+2 into stage consumed at it-1 — both safe past head sync.
        if (it + 1 < 8) stsA(ab[(it+1)&1], rw, c16, pf, ss);
        if (it + 2 < 8){
            pf[0] = *reinterpret_cast<const float4*>(Ag + (it+2)*64);
            pf[1] = *reinterpret_cast<const float4*>(Ag + (size_t)32*DD + (it+2)*64);
            int nb = b3 + 2; if (nb >= 3) nb -= 3;
            issueB(it + 2, bbuf[nb], tid);
        }
        b3++; if (b3 >= 3) b3 -= 3;
    }
    __syncthreads();                     // stages dead; s_t overlay begins

    // patch norms: reduce sumsq over the 16-lane group sharing each row
    #pragma unroll
    for (int i = 0; i < 2; i++){
        float s = ss[i];
        s += __shfl_xor_sync(0xffffffffu, s, 1);
        s += __shfl_xor_sync(0xffffffffu, s, 2);
        s += __shfl_xor_sync(0xffffffffu, s, 4);
        s += __shfl_xor_sync(0xffffffffu, s, 8);
        if (c16 == 0) s_rnp[rw + 32*i] = 1.0f / fmaxf(sqrtf(s), 1e-12f);
    }
    __syncthreads();

    // ---- epilogue: scale, softmax over full 512 cols, normalized fp16 store
    float rs[2][2], rt[8][2];
    #pragma unroll
    for (int mi = 0; mi < 2; mi++)
        #pragma unroll
        for (int h = 0; h < 2; h++)
            rs[mi][h] = s_rnp[mw*32 + mi*16 + h*8 + gid] * INV_TEMP;
    #pragma unroll
    for (int j = 0; j < 8; j++){
        int c0 = nw*64 + j*8 + tig*2;
        rt[j][0] = s_rnt[c0]; rt[j][1] = s_rnt[c0+1];
    }
    #pragma unroll
    for (int mi = 0; mi < 2; mi++)
        #pragma unroll
        for (int j = 0; j < 8; j++)
            #pragma unroll
            for (int v = 0; v < 4; v++)
                acc[mi][j][v] *= rs[mi][v>>1] * rt[j][v&1];

    // per-row max (warp slice over its 64 cols), quad shuffle, 8-warp smem reduce
    #pragma unroll
    for (int mi = 0; mi < 2; mi++)
        #pragma unroll
        for (int h = 0; h < 2; h++){
            float mx = -3.0e38f;
            #pragma unroll
            for (int j = 0; j < 8; j++)
                mx = fmaxf(mx, fmaxf(acc[mi][j][2*h], acc[mi][j][2*h+1]));
            mx = fmaxf(mx, __shfl_xor_sync(0xffffffffu, mx, 1));
            mx = fmaxf(mx, __shfl_xor_sync(0xffffffffu, mx, 2));
            if (tig == 0) s_red[(mw*32 + mi*16 + h*8 + gid)*8 + nw] = mx;
        }
    __syncthreads();
    if (tid < 64){
        float m = s_red[tid*8];
        #pragma unroll
        for (int k = 1; k < 8; k++) m = fmaxf(m, s_red[tid*8 + k]);
        s_gmax[tid] = m;
    }
    __syncthreads();

    // exp + row sum
    #pragma unroll
    for (int mi = 0; mi < 2; mi++)
        #pragma unroll
        for (int h = 0; h < 2; h++){
            float gm = s_gmax[mw*32 + mi*16 + h*8 + gid];
            float sm = 0.f;
            #pragma unroll
            for (int j = 0; j < 8; j++){
                float e0 = __expf(acc[mi][j][2*h]   - gm);
                float e1 = __expf(acc[mi][j][2*h+1] - gm);
                acc[mi][j][2*h] = e0; acc[mi][j][2*h+1] = e1;
                sm += e0 + e1;
            }
            sm += __shfl_xor_sync(0xffffffffu, sm, 1);
            sm += __shfl_xor_sync(0xffffffffu, sm, 2);
            if (tig == 0) s_red[(mw*32 + mi*16 + h*8 + gid)*8 + nw] = sm;
        }
    __syncthreads();
    if (tid < 64){
        float s = 0.f;
        #pragma unroll
        for (int k = 0; k < 8; k++) s += s_red[tid*8 + k];
        s_rzv[tid] = 1.0f / s;
    }
    __syncthreads();

    // normalized transposed store into padded smem [c][n], stride 68
    #pragma unroll
    for (int mi = 0; mi < 2; mi++)
        #pragma unroll
        for (int j = 0; j < 8; j++)
            #pragma unroll
            for (int v = 0; v < 4; v++){
                int col = nw*64 + j*8 + tig*2 + (v&1);
                int row = mw*32 + mi*16 + (v>>1)*8 + gid;
                s_t[col*68 + row] = acc[mi][j][v] * s_rzv[row];
            }
    __syncthreads();

    // vectorized coalesced fp16 copy-out: g_aff[b][c][nt*64 + n], 16B stores
    __half* obase = g_aff + (size_t)b * CC * NN + (size_t)nt * 64;
    const int cpart = tid >> 3;           // 0..63
    const int n8    = (tid & 7) * 8;      // 0..56
    #pragma unroll
    for (int itc = 0; itc < 8; itc++){
        int c = itc*64 + cpart;
        float4 f0 = *reinterpret_cast<const float4*>(&s_t[c*68 + n8]);
        float4 f1 = *reinterpret_cast<const float4*>(&s_t[c*68 + n8 + 4]);
        union { __half2 h[4]; uint4 u; } U;
        U.h[0] = __floats2half2_rn(f0.x, f0.y);
        U.h[1] = __floats2half2_rn(f0.z, f0.w);
        U.h[2] = __floats2half2_rn(f1.x, f1.y);
        U.h[3] = __floats2half2_rn(f1.z, f1.w);
        *reinterpret_cast<uint4*>(obase + (size_t)c * NN + n8) = U.u;
    }
}

// ================= kernel 4: top-16 over N per (b,c), blend ==================
// Per-lane value + chunk-key arrays live in SMEM (warp-private, no barriers).
// key = (fp16bits << 16) | (lane << 3) | chunk
__global__ __launch_bounds__(256) void topk_kernel(float* __restrict__ out){
    __shared__ uint32_t s_v[8][16][32];   // [warp][reg][lane]  values (reg-major)
    __shared__ uint32_t s_k[8][32][8];    // [warp][lane][chunk] keys (lane-major)

    const int wip  = threadIdx.x >> 5;                  // warp in block
    const int lane = threadIdx.x & 31;
    const int w    = blockIdx.x * 8 + wip;              // b*512 + c
    if (w >= BB*CC) return;
    const uint4* p = reinterpret_cast<const uint4*>(g_aff + (size_t)w * NN);

    uint32_t (*V)[32] = s_v[wip];
    uint32_t* K = s_k[wip][lane];

    unsigned lk = 0;
    #pragma unroll
    for (int j = 0; j < 4; j++){
        uint4 q = p[j*32 + lane];
        V[4*j+0][lane] = q.x; V[4*j+1][lane] = q.y;
        V[4*j+2][lane] = q.z; V[4*j+3][lane] = q.w;
        unsigned m0 = __vmaxu2(q.x, q.y);
        unsigned mv0 = umax2(m0 & 0xFFFFu, m0 >> 16);
        unsigned k0 = (mv0 << 16) | ((unsigned)lane << 3) | (unsigned)(2*j);
        unsigned m1 = __vmaxu2(q.z, q.w);
        unsigned mv1 = umax2(m1 & 0xFFFFu, m1 >> 16);
        unsigned k1 = (mv1 << 16) | ((unsigned)lane << 3) | (unsigned)(2*j + 1);
        K[2*j] = k0; K[2*j+1] = k1;
        lk = umax2(lk, umax2(k0, k1));
    }

    float sum = 0.f;
    #pragma unroll
    for (int it = 0; it < KTOP; ++it){
        unsigned m;
        asm("redux.sync.max.u32 %0, %1, 0xffffffff;" : "=r"(m) : "r"(lk));
        __half_raw hr; hr.x = (unsigned short)(m >> 16);
        sum += __half2float(*reinterpret_cast<__half*>(&hr));
        if (((m >> 3) & 31u) == (unsigned)lane){
            const unsigned val = m >> 16;
            const int oc = (int)(m & 7u);
            unsigned v0 = V[2*oc  ][lane];
            unsigned v1 = V[2*oc+1][lane];
            if      ((v0 & 0xFFFFu) == val) v0 &= 0xFFFF0000u;
            else if ((v0 >> 16)     == val) v0 &= 0x0000FFFFu;
            else if ((v1 & 0xFFFFu) == val) v1 &= 0xFFFF0000u;
            else                            v1 &= 0x0000FFFFu;
            V[2*oc  ][lane] = v0;
            V[2*oc+1][lane] = v1;
            unsigned m2 = __vmaxu2(v0, v1);
            unsigned mv = umax2(m2 & 0xFFFFu, m2 >> 16);
            K[oc] = (mv << 16) | ((unsigned)lane << 3) | (unsigned)oc;
            uint4 ka = *reinterpret_cast<uint4*>(&K[0]);
            uint4 kb = *reinterpret_cast<uint4*>(&K[4]);
            unsigned t0 = umax2(ka.x, ka.y), t1 = umax2(ka.z, ka.w);
            unsigned t2 = umax2(kb.x, kb.y), t3 = umax2(kb.z, kb.w);
            lk = umax2(umax2(t0, t1), umax2(t2, t3));
        }
    }
    if (lane == 0) out[w] += 0.7f * (sum * (1.0f / (float)KTOP));
}

// ================= launch =====================================================
extern "C" void kernel_launch(void* const* d_in, const int* in_sizes, int n_in,
                              void* d_out, int out_size){
    const float* vcls = nullptr;
    const float* vp   = nullptr;
    const float* text = nullptr;
    for (int i = 0; i < n_in; i++){
        if      (in_sizes[i] == BB*DD)     vcls = (const float*)d_in[i];
        else if (in_sizes[i] == BB*NN*DD)  vp   = (const float*)d_in[i];
        else if (in_sizes[i] == CC*DD)     text = (const float*)d_in[i];
    }
    float* out = (float*)d_out;

    cudaFuncSetAttribute(gemm_softmax_kernel,
                         cudaFuncAttributeMaxDynamicSharedMemorySize, SM_DYN);

    const int nwarps = CC + BB;
    convert_kernel<<<(nwarps*32 + 255)/256, 256>>>(vcls, text);
    affg_kernel<<<BB, 512>>>(vcls, out);
    gemm_softmax_kernel<<<1024, 512, SM_DYN>>>(vp);
    topk_kernel<<<(BB*CC)/8, 256>>>(out);
}

// round 17
// speedup vs baseline: 1.2148x; 1.0347x over previous
#include <cuda_runtime.h>
#include <cuda_fp16.h>
#include <math.h>
#include <stdint.h>

#define BB 64
#define NN 1024
#define DD 512
#define CC 512
#define KTOP 16
#define INV_TEMP (1.0f/0.07f)

// ---------------- scratch (device globals: no allocations allowed) ----------
__device__ __half g_aff[(size_t)BB * CC * NN];    // [b][c][n] normalized softmax p (fp16)
__device__ float g_rnt[CC];
__device__ float g_rnc[BB];
__device__ __half g_txh[(size_t)CC*DD];           // text fp16

// ================= helpers ====================================================
static __device__ __forceinline__ uint32_t smem_u32(const void* p){
    uint32_t a;
    asm("{ .reg .u64 t; cvta.to.shared.u64 t, %1; cvt.u32.u64 %0, t; }" : "=r"(a) : "l"(p));
    return a;
}
static __device__ __forceinline__ void cpasync16(uint32_t dst, const void* src){
    asm volatile("cp.async.cg.shared.global [%0], [%1], 16;" :: "r"(dst), "l"(src) : "memory");
}
static __device__ __forceinline__ uint32_t swz(uint32_t o){ return o ^ ((o >> 3) & 0x70u); }

static __device__ __forceinline__ void ldsm4(uint32_t &r0, uint32_t &r1,
                                             uint32_t &r2, uint32_t &r3, uint32_t addr){
    asm volatile("ldmatrix.sync.aligned.m8n8.x4.shared.b16 {%0,%1,%2,%3}, [%4];"
        : "=r"(r0), "=r"(r1), "=r"(r2), "=r"(r3) : "r"(addr));
}
static __device__ __forceinline__ void mma16816(float* d, const uint32_t* a,
                                                uint32_t b0, uint32_t b1){
    asm volatile("mma.sync.aligned.m16n8k16.row.col.f32.f16.f16.f32 "
        "{%0,%1,%2,%3}, {%4,%5,%6,%7}, {%8,%9}, {%0,%1,%2,%3};"
        : "+f"(d[0]), "+f"(d[1]), "+f"(d[2]), "+f"(d[3])
        : "r"(a[0]), "r"(a[1]), "r"(a[2]), "r"(a[3]), "r"(b0), "r"(b1));
}
static __device__ __forceinline__ unsigned umax2(unsigned a, unsigned b){ return a > b ? a : b; }

// ================= kernel 1: text fp16 convert + text/cls L2 norms ===========
__global__ void convert_kernel(const float* __restrict__ vcls,
                               const float* __restrict__ text){
    int w    = (blockIdx.x * blockDim.x + threadIdx.x) >> 5;
    int lane = threadIdx.x & 31;
    const int NW = CC + BB;
    if (w >= NW) return;
    const float* src; __half* hi = nullptr; float* rdst;
    if (w < CC){ src = text + (size_t)w*DD; hi = g_txh + (size_t)w*DD; rdst = g_rnt + w; }
    else       { int ci = w - CC; src = vcls + (size_t)ci*DD; rdst = g_rnc + ci; }
    float ss = 0.f;
    #pragma unroll
    for (int j = 0; j < 4; j++){
        int o = (j*32 + lane) * 4;
        float4 v = *reinterpret_cast<const float4*>(src + o);
        ss += v.x*v.x + v.y*v.y + v.z*v.z + v.w*v.w;
        if (hi){
            union { __half2 h2[2]; uint2 u; } P;
            P.h2[0] = __floats2half2_rn(v.x, v.y);
            P.h2[1] = __floats2half2_rn(v.z, v.w);
            *reinterpret_cast<uint2*>(hi + o) = P.u;
        }
    }
    #pragma unroll
    for (int off = 16; off; off >>= 1) ss += __shfl_xor_sync(0xffffffffu, ss, off);
    if (lane == 0) *rdst = 1.0f / fmaxf(sqrtf(ss), 1e-12f);
}

// ================= kernel 2: global affinity, writes 0.3*softmax ============
// text read as fp16 (g_txh) — runs after convert_kernel.
__global__ __launch_bounds__(512) void affg_kernel(const float* __restrict__ vcls,
                                                   float* __restrict__ out){
    __shared__ float sv[DD];
    __shared__ float red[16];
    int b = blockIdx.x, tid = threadIdx.x;
    sv[tid] = vcls[b*DD + tid];
    __syncthreads();
    const uint4* t4 = reinterpret_cast<const uint4*>(g_txh + (size_t)tid * DD);
    float dot = 0.f;
    #pragma unroll 8
    for (int k = 0; k < 64; k++){
        uint4 q = t4[k];
        float2 f0 = __half22float2(*reinterpret_cast<__half2*>(&q.x));
        float2 f1 = __half22float2(*reinterpret_cast<__half2*>(&q.y));
        float2 f2 = __half22float2(*reinterpret_cast<__half2*>(&q.z));
        float2 f3 = __half22float2(*reinterpret_cast<__half2*>(&q.w));
        const float* s = &sv[k*8];
        dot += f0.x*s[0] + f0.y*s[1] + f1.x*s[2] + f1.y*s[3]
             + f2.x*s[4] + f2.y*s[5] + f3.x*s[6] + f3.y*s[7];
    }
    float logit = dot * g_rnc[b] * g_rnt[tid] * INV_TEMP;
    int lane = tid & 31, wid = tid >> 5;
    float m = logit;
    #pragma unroll
    for (int off = 16; off; off >>= 1) m = fmaxf(m, __shfl_xor_sync(0xffffffffu, m, off));
    if (lane == 0) red[wid] = m;
    __syncthreads();
    float bm = red[0];
    #pragma unroll
    for (int i = 1; i < 16; i++) bm = fmaxf(bm, red[i]);
    __syncthreads();
    float e = __expf(logit - bm);
    float s = e;
    #pragma unroll
    for (int off = 16; off; off >>= 1) s += __shfl_xor_sync(0xffffffffu, s, off);
    if (lane == 0) red[wid] = s;
    __syncthreads();
    float bs = 0.f;
    #pragma unroll
    for (int i = 0; i < 16; i++) bs += red[i];
    out[b*CC + tid] = 0.3f * e / bs;
}

// ================= kernel 3: fp16 HMMA GEMM, 16 warps, fused A ==============
// CTA: 64 patches x 512 classes, 512 threads (16 warps: mw=wid>>3, nw=wid&7).
// Warp tile 32x64. kc=64, 8 k-iters. B triple-buffered, A double-buffered,
// head-barrier-only pipeline (loads issued AFTER the MMA region, no tail sync).
#define SM_A0   0u
#define SM_A1   8192u
#define SM_B0   16384u
#define SM_B1   81920u
#define SM_B2   147456u
#define SM_AUX  212992u
#define SM_DYN  (212992u + 4864u + 1024u)

static __device__ __forceinline__ void issueB(int kt, uint32_t b_dst, int tid){
    const __half* Bb = g_txh + kt * 64;
    #pragma unroll
    for (int t = 0; t < 8; t++){   // B: 512 rows x 128B = 4096 chunks / 512 thr
        int g = tid + t*512; int row = g >> 3; int c = g & 7;
        cpasync16(b_dst + swz(row*128 + c*16), Bb + (size_t)row*DD + c*8);
    }
    asm volatile("cp.async.commit_group;" ::: "memory");
}

// convert & store 2 rows' chunks of A (rows rw, rw+32; 16B chunk c16), sumsq
static __device__ __forceinline__ void stsA(uint32_t abase, int rw, int c16,
                                            const float4* pf, float* ss){
    #pragma unroll
    for (int i = 0; i < 2; i++){
        union { __half2 h2; uint32_t u; } P0, P1;
        P0.h2 = __floats2half2_rn(pf[i].x, pf[i].y);
        P1.h2 = __floats2half2_rn(pf[i].z, pf[i].w);
        ss[i] += pf[i].x*pf[i].x + pf[i].y*pf[i].y + pf[i].z*pf[i].z + pf[i].w*pf[i].w;
        uint32_t off = (uint32_t)((rw + 32*i)*128 + c16*8);
        asm volatile("st.shared.v2.b32 [%0], {%1,%2};"
            :: "r"(abase + swz(off)), "r"(P0.u), "r"(P1.u) : "memory");
    }
}

__global__ __launch_bounds__(512, 1) void gemm_softmax_kernel(const float* __restrict__ vp){
    extern __shared__ __align__(16) char dsm[];
    const uint32_t raw  = smem_u32(dsm);
    const uint32_t base = (raw + 1023u) & ~1023u;
    char* bp = dsm + (base - raw);

    const int tid = threadIdx.x;
    const int pb  = blockIdx.x;          // 0..1023
    const int b   = pb >> 4;
    const int nt  = pb & 15;

    const uint32_t ab[2]   = { base + SM_A0, base + SM_A1 };
    const uint32_t bbuf[3] = { base + SM_B0, base + SM_B1, base + SM_B2 };
    float* s_t    = reinterpret_cast<float*>(bp);                    // 512*68 f (overlays stages)
    float* s_rnt  = reinterpret_cast<float*>(bp + SM_AUX);           // 512 f
    float* s_rnp  = reinterpret_cast<float*>(bp + SM_AUX + 2048);    // 64 f
    float* s_red  = reinterpret_cast<float*>(bp + SM_AUX + 2304);    // 8*64 f (nw-major)
    float* s_gmax = reinterpret_cast<float*>(bp + SM_AUX + 4352);    // 64 f
    float* s_rzv  = reinterpret_cast<float*>(bp + SM_AUX + 4608);    // 64 f

    const int wid  = tid >> 5;
    const int lane = tid & 31;
    const int mw   = wid >> 3;           // 0..1
    const int nw   = wid & 7;            // 0..7
    const int gid  = lane >> 2;          // row group 0..7
    const int tig  = lane & 3;

    if (tid < 512) s_rnt[tid] = g_rnt[tid];

    // fused A path: 1024 float4 chunks per k-tile, 2 per thread (rows rw, rw+32)
    const int c16 = tid & 15;            // 16B chunk within 64-float slab row
    const int rw  = tid >> 4;            // row 0..31; second row = rw+32
    const float* Ag = vp + ((size_t)(pb*64 + rw))*DD + c16*4;

    float4 pf[2];
    pf[0] = *reinterpret_cast<const float4*>(Ag);
    pf[1] = *reinterpret_cast<const float4*>(Ag + (size_t)32*DD);

    issueB(0, bbuf[0], tid);
    issueB(1, bbuf[1], tid);

    float ss[2] = {0.f, 0.f};
    stsA(ab[0], rw, c16, pf, ss);                        // A tile for kt=0
    pf[0] = *reinterpret_cast<const float4*>(Ag + 64);
    pf[1] = *reinterpret_cast<const float4*>(Ag + (size_t)32*DD + 64);

    // ldmatrix lane addressing (canonical x4 fragment order)
    const int lr = (lane & 7) + ((lane >> 3) & 1) * 8;   // row within 16
    const int lk = (lane >> 4) * 16;                     // 16B col half

    float acc[2][8][4];
    #pragma unroll
    for (int mi = 0; mi < 2; mi++)
        #pragma unroll
        for (int j = 0; j < 8; j++)
            #pragma unroll
            for (int v = 0; v < 4; v++) acc[mi][j][v] = 0.f;

    int b3 = 0;                          // it % 3
    for (int it = 0; it < 8; ++it){
        if (it == 7) asm volatile("cp.async.wait_group 0;" ::: "memory");
        else         asm volatile("cp.async.wait_group 1;" ::: "memory");
        __syncthreads();                 // head barrier (the only one per iter)

        const uint32_t abase = ab[it & 1];
        const uint32_t bbase = bbuf[b3];
        #pragma unroll
        for (int ks = 0; ks < 4; ks++){
            uint32_t af[2][4];
            #pragma unroll
            for (int mi = 0; mi < 2; mi++){
                int r = mw*32 + mi*16 + lr;
                ldsm4(af[mi][0], af[mi][1], af[mi][2], af[mi][3],
                      abase + swz((uint32_t)(r*128 + ks*32 + lk)));
            }
            uint32_t bf[4][4];
            #pragma unroll
            for (int jj = 0; jj < 4; jj++){
                int r = nw*64 + jj*16 + lr;
                ldsm4(bf[jj][0], bf[jj][1], bf[jj][2], bf[jj][3],
                      bbase + swz((uint32_t)(r*128 + ks*32 + lk)));
            }
            #pragma unroll
            for (int mi = 0; mi < 2; mi++)
                #pragma unroll
                for (int j = 0; j < 8; j++)
                    mma16816(acc[mi][j], af[mi], bf[j>>1][j&1], bf[j>>1][(j&1)+2]);
        }
        // post-MMA, no tail barrier: write A for it+1 (buffer consumed at it-1),
        // issue B for it+2 into stage consumed at it-1 — both safe past head sync.
        if (it + 1 < 8) stsA(ab[(it+1)&1], rw, c16, pf, ss);
        if (it + 2 < 8){
            pf[0] = *reinterpret_cast<const float4*>(Ag + (it+2)*64);
            pf[1] = *reinterpret_cast<const float4*>(Ag + (size_t)32*DD + (it+2)*64);
            int nb = b3 + 2; if (nb >= 3) nb -= 3;
            issueB(it + 2, bbuf[nb], tid);
        }
        b3++; if (b3 >= 3) b3 -= 3;
    }
    __syncthreads();                     // stages dead; s_t overlay begins

    // patch norms: reduce sumsq over the 16-lane group sharing each row
    #pragma unroll
    for (int i = 0; i < 2; i++){
        float s = ss[i];
        s += __shfl_xor_sync(0xffffffffu, s, 1);
        s += __shfl_xor_sync(0xffffffffu, s, 2);
        s += __shfl_xor_sync(0xffffffffu, s, 4);
        s += __shfl_xor_sync(0xffffffffu, s, 8);
        if (c16 == 0) s_rnp[rw + 32*i] = 1.0f / fmaxf(sqrtf(s), 1e-12f);
    }
    __syncthreads();

    // ---- epilogue: scale, softmax over full 512 cols, normalized fp16 store
    float rs[2][2], rt[8][2];
    #pragma unroll
    for (int mi = 0; mi < 2; mi++)
        #pragma unroll
        for (int h = 0; h < 2; h++)
            rs[mi][h] = s_rnp[mw*32 + mi*16 + h*8 + gid] * INV_TEMP;
    #pragma unroll
    for (int j = 0; j < 8; j++){
        int c0 = nw*64 + j*8 + tig*2;
        rt[j][0] = s_rnt[c0]; rt[j][1] = s_rnt[c0+1];
    }
    #pragma unroll
    for (int mi = 0; mi < 2; mi++)
        #pragma unroll
        for (int j = 0; j < 8; j++)
            #pragma unroll
            for (int v = 0; v < 4; v++)
                acc[mi][j][v] *= rs[mi][v>>1] * rt[j][v&1];

    // per-row max (warp slice over its 64 cols), quad shuffle, 8-warp smem reduce
    // s_red layout nw-major: s_red[nw*64 + row] — conflict-free writes AND reads
    #pragma unroll
    for (int mi = 0; mi < 2; mi++)
        #pragma unroll
        for (int h = 0; h < 2; h++){
            float mx = -3.0e38f;
            #pragma unroll
            for (int j = 0; j < 8; j++)
                mx = fmaxf(mx, fmaxf(acc[mi][j][2*h], acc[mi][j][2*h+1]));
            mx = fmaxf(mx, __shfl_xor_sync(0xffffffffu, mx, 1));
            mx = fmaxf(mx, __shfl_xor_sync(0xffffffffu, mx, 2));
            if (tig == 0) s_red[nw*64 + (mw*32 + mi*16 + h*8 + gid)] = mx;
        }
    __syncthreads();
    if (tid < 64){
        float m = s_red[tid];
        #pragma unroll
        for (int k = 1; k < 8; k++) m = fmaxf(m, s_red[k*64 + tid]);
        s_gmax[tid] = m;
    }
    __syncthreads();

    // exp + row sum
    #pragma unroll
    for (int mi = 0; mi < 2; mi++)
        #pragma unroll
        for (int h = 0; h < 2; h++){
            float gm = s_gmax[mw*32 + mi*16 + h*8 + gid];
            float sm = 0.f;
            #pragma unroll
            for (int j = 0; j < 8; j++){
                float e0 = __expf(acc[mi][j][2*h]   - gm);
                float e1 = __expf(acc[mi][j][2*h+1] - gm);
                acc[mi][j][2*h] = e0; acc[mi][j][2*h+1] = e1;
                sm += e0 + e1;
            }
            sm += __shfl_xor_sync(0xffffffffu, sm, 1);
            sm += __shfl_xor_sync(0xffffffffu, sm, 2);
            if (tig == 0) s_red[nw*64 + (mw*32 + mi*16 + h*8 + gid)] = sm;
        }
    __syncthreads();
    if (tid < 64){
        float s = 0.f;
        #pragma unroll
        for (int k = 0; k < 8; k++) s += s_red[k*64 + tid];
        s_rzv[tid] = 1.0f / s;
    }
    __syncthreads();

    // normalized transposed store into padded smem [c][n], stride 68
    #pragma unroll
    for (int mi = 0; mi < 2; mi++)
        #pragma unroll
        for (int j = 0; j < 8; j++)
            #pragma unroll
            for (int v = 0; v < 4; v++){
                int col = nw*64 + j*8 + tig*2 + (v&1);
                int row = mw*32 + mi*16 + (v>>1)*8 + gid;
                s_t[col*68 + row] = acc[mi][j][v] * s_rzv[row];
            }
    __syncthreads();

    // vectorized coalesced fp16 copy-out: g_aff[b][c][nt*64 + n] (r13 version)
    __half* obase = g_aff + (size_t)b * CC * NN + (size_t)nt * 64;
    const int cpart = tid >> 4;           // 0..31
    const int n4    = (tid & 15) * 4;     // 0..60
    #pragma unroll 4
    for (int itc = 0; itc < 16; itc++){
        int c = itc*32 + cpart;
        float4 f = *reinterpret_cast<const float4*>(&s_t[c*68 + n4]);
        union { __half2 h[2]; uint2 u; } U;
        U.h[0] = __floats2half2_rn(f.x, f.y);
        U.h[1] = __floats2half2_rn(f.z, f.w);
        *reinterpret_cast<uint2*>(obase + (size_t)c * NN + n4) = U.u;
    }
}

// ================= kernel 4: top-16 over N per (b,c), blend ==================
// Per-lane value + chunk-key arrays live in SMEM (warp-private, no barriers).
// key = (fp16bits << 16) | (lane << 3) | chunk
__global__ __launch_bounds__(256) void topk_kernel(float* __restrict__ out){
    __shared__ uint32_t s_v[8][16][32];   // [warp][reg][lane]  values (reg-major)
    __shared__ uint32_t s_k[8][32][8];    // [warp][lane][chunk] keys (lane-major)

    const int wip  = threadIdx.x >> 5;                  // warp in block
    const int lane = threadIdx.x & 31;
    const int w    = blockIdx.x * 8 + wip;              // b*512 + c
    if (w >= BB*CC) return;
    const uint4* p = reinterpret_cast<const uint4*>(g_aff + (size_t)w * NN);

    uint32_t (*V)[32] = s_v[wip];
    uint32_t* K = s_k[wip][lane];

    unsigned lk = 0;
    #pragma unroll
    for (int j = 0; j < 4; j++){
        uint4 q = p[j*32 + lane];
        V[4*j+0][lane] = q.x; V[4*j+1][lane] = q.y;
        V[4*j+2][lane] = q.z; V[4*j+3][lane] = q.w;
        unsigned m0 = __vmaxu2(q.x, q.y);
        unsigned mv0 = umax2(m0 & 0xFFFFu, m0 >> 16);
        unsigned k0 = (mv0 << 16) | ((unsigned)lane << 3) | (unsigned)(2*j);
        unsigned m1 = __vmaxu2(q.z, q.w);
        unsigned mv1 = umax2(m1 & 0xFFFFu, m1 >> 16);
        unsigned k1 = (mv1 << 16) | ((unsigned)lane << 3) | (unsigned)(2*j + 1);
        K[2*j] = k0; K[2*j+1] = k1;
        lk = umax2(lk, umax2(k0, k1));
    }

    float sum = 0.f;
    #pragma unroll
    for (int it = 0; it < KTOP; ++it){
        unsigned m;
        asm("redux.sync.max.u32 %0, %1, 0xffffffff;" : "=r"(m) : "r"(lk));
        __half_raw hr; hr.x = (unsigned short)(m >> 16);
        sum += __half2float(*reinterpret_cast<__half*>(&hr));
        if (((m >> 3) & 31u) == (unsigned)lane){
            const unsigned val = m >> 16;
            const int oc = (int)(m & 7u);
            unsigned v0 = V[2*oc  ][lane];
            unsigned v1 = V[2*oc+1][lane];
            if      ((v0 & 0xFFFFu) == val) v0 &= 0xFFFF0000u;
            else if ((v0 >> 16)     == val) v0 &= 0x0000FFFFu;
            else if ((v1 & 0xFFFFu) == val) v1 &= 0xFFFF0000u;
            else                            v1 &= 0x0000FFFFu;
            V[2*oc  ][lane] = v0;
            V[2*oc+1][lane] = v1;
            unsigned m2 = __vmaxu2(v0, v1);
            unsigned mv = umax2(m2 & 0xFFFFu, m2 >> 16);
            K[oc] = (mv << 16) | ((unsigned)lane << 3) | (unsigned)oc;
            uint4 ka = *reinterpret_cast<uint4*>(&K[0]);
            uint4 kb = *reinterpret_cast<uint4*>(&K[4]);
            unsigned t0 = umax2(ka.x, ka.y), t1 = umax2(ka.z, ka.w);
            unsigned t2 = umax2(kb.x, kb.y), t3 = umax2(kb.z, kb.w);
            lk = umax2(umax2(t0, t1), umax2(t2, t3));
        }
    }
    if (lane == 0) out[w] += 0.7f * (sum * (1.0f / (float)KTOP));
}

// ================= launch =====================================================
extern "C" void kernel_launch(void* const* d_in, const int* in_sizes, int n_in,
                              void* d_out, int out_size){
    const float* vcls = nullptr;
    const float* vp   = nullptr;
    const float* text = nullptr;
    for (int i = 0; i < n_in; i++){
        if      (in_sizes[i] == BB*DD)     vcls = (const float*)d_in[i];
        else if (in_sizes[i] == BB*NN*DD)  vp   = (const float*)d_in[i];
        else if (in_sizes[i] == CC*DD)     text = (const float*)d_in[i];
    }
    float* out = (float*)d_out;

    cudaFuncSetAttribute(gemm_softmax_kernel,
                         cudaFuncAttributeMaxDynamicSharedMemorySize, SM_DYN);

    const int nwarps = CC + BB;
    convert_kernel<<<(nwarps*32 + 255)/256, 256>>>(vcls, text);
    affg_kernel<<<BB, 512>>>(vcls, out);
    gemm_softmax_kernel<<<1024, 512, SM_DYN>>>(vp);
    topk_kernel<<<(BB*CC)/8, 256>>>(out);
}